// round 11
// baseline (speedup 1.0000x reference)
#include <cuda_runtime.h>
#include <cuda_fp16.h>
#include <cstdint>

#define BB 32
#define TT 8192
#define DD 256
#define UU 128
#define MT 128
#define NCTA ((BB * TT) / MT)   // 2048 tiles, 64 per batch
#define PGRID 296               // persistent grid: 2 CTAs/SM, resident on 148+ SMs

#define AROW 528                 // A row stride BYTES: 512 payload + 16 pad
// ---- dynamic SMEM layout (bytes) ----
#define A_OFF   0                // 128 rows x 528B = 67584 (full fp16 tile)
#define B_OFF   67584            // 4 x (128 rows x 80B) = 40960
#define SC_OFF  108544           // [2][128] floats = 1024
#define ES_OFF  109568           // 128 floats
#define HQ_OFF  110080           // 128 floats
#define B1_OFF  110592           // 128 floats
#define VV_OFF  111104           // 128 floats
#define RED_OFF 111616           // 64 floats
#define SMEM_BYTES 112128

// ---- scratch globals (allocation-free) ----
__device__ float  g_hq[BB * UU];
__device__ __half g_W1h[UU * DD];       // W1 transposed -> [u][d], fp16
__device__ float  g_scores[BB * TT];
__device__ float  g_stats[NCTA * 2];    // per-tile (local max, local expsum)
__device__ float  g_pctx[NCTA * DD];    // per-tile unnormalized partial context
__device__ float  g_bstats[BB * 2];     // per-batch (global max, 1/sum)

// ---------------------------------------------------------------------------
// helpers
// ---------------------------------------------------------------------------
__device__ __forceinline__ uint32_t smem_u32(const void* p) {
    uint32_t a;
    asm("{ .reg .u64 t; cvta.to.shared.u64 t, %1; cvt.u32.u64 %0, t; }" : "=r"(a) : "l"(p));
    return a;
}
__device__ __forceinline__ void ldsm4(uint32_t (&r)[4], uint32_t addr) {
    asm volatile("ldmatrix.sync.aligned.m8n8.x4.shared.b16 {%0,%1,%2,%3}, [%4];"
                 : "=r"(r[0]), "=r"(r[1]), "=r"(r[2]), "=r"(r[3]) : "r"(addr));
}
__device__ __forceinline__ void mma_f16(float c[4],
                                        uint32_t a0, uint32_t a1, uint32_t a2, uint32_t a3,
                                        uint32_t b0, uint32_t b1) {
    asm volatile(
        "mma.sync.aligned.m16n8k16.row.col.f32.f16.f16.f32 "
        "{%0,%1,%2,%3}, {%4,%5,%6,%7}, {%8,%9}, {%0,%1,%2,%3};"
        : "+f"(c[0]), "+f"(c[1]), "+f"(c[2]), "+f"(c[3])
        : "r"(a0), "r"(a1), "r"(a2), "r"(a3), "r"(b0), "r"(b1));
}
__device__ __forceinline__ void cp16(uint32_t dst, const void* src) {
    asm volatile("cp.async.cg.shared.global [%0], [%1], 16;"
                 :: "r"(dst), "l"(src) : "memory");
}
__device__ __forceinline__ void cp_commit() {
    asm volatile("cp.async.commit_group;" ::: "memory");
}
__device__ __forceinline__ void cp_wait0() {
    asm volatile("cp.async.wait_group 0;" ::: "memory");
}
__device__ __forceinline__ uint32_t h2_bits(__half2 h) {
    union { __half2 h; uint32_t u; } cvt;
    cvt.h = h;
    return cvt.u;
}
__device__ __forceinline__ float tanh_fast(float x) {   // 1 MUFU, ~5e-4 abs err
    float y;
    asm("tanh.approx.f32 %0, %1;" : "=f"(y) : "f"(x));
    return y;
}

// ---------------------------------------------------------------------------
// fused prep: blocks 0..31 -> hq, blocks 32..159 -> W1 transpose+fp16
// ---------------------------------------------------------------------------
__global__ void prep_kernel(const float* __restrict__ query,
                            const float* __restrict__ W2,
                            const float* __restrict__ W2b,
                            const float* __restrict__ W1) {
    if (blockIdx.x < 32) {
        if (threadIdx.x < UU) {
            int b = blockIdx.x, u = threadIdx.x;
            const float* q = query + b * DD;
            float acc = 0.0f;
#pragma unroll 8
            for (int d = 0; d < DD; d++) acc += q[d] * W2[d * UU + u];
            g_hq[b * UU + u] = fmaxf(acc + W2b[u], 0.0f);
        }
    } else {
        int u = blockIdx.x - 32, d = threadIdx.x;
        g_W1h[u * DD + d] = __float2half_rn(W1[d * UU + u]);
    }
}

// ---------------------------------------------------------------------------
// persistent fused kernel: per tile, scores (fp16 mma) + local softmax +
// partial context. 296 CTAs x 256 threads; each CTA walks tiles bid+296k.
// warp = (rg 0..3, ch 0..1): rows [32*rg,+32) x cols [64*ch,+64).
// ---------------------------------------------------------------------------
__global__ __launch_bounds__(256, 2)
void scores_kernel(const float* __restrict__ values,
                   const float* __restrict__ W1b,
                   const float* __restrict__ Vk,
                   const float* __restrict__ Vb) {
    extern __shared__ char smem[];
    const uint32_t sbase = smem_u32(smem);
    const int tid  = threadIdx.x;
    const int wid  = tid >> 5;
    const int lane = tid & 31;
    const int rg   = wid >> 1;
    const int ch   = wid & 1;
    const int mrow = lane & 7;
    const int mi   = lane >> 3;
    const int tg   = lane & 3;
    const int g    = lane >> 2;

    float* s_sc = (float*)(smem + SC_OFF);
    float* s_es = (float*)(smem + ES_OFF);
    float* s_hq = (float*)(smem + HQ_OFF);
    float* s_b1 = (float*)(smem + B1_OFF);
    float* s_v  = (float*)(smem + VV_OFF);
    float* s_rd = (float*)(smem + RED_OFF);

    // ---- staging helpers ----
    auto stageB = [&](int c) {                   // cp.async, 4-buffer ring
        const uint32_t base = sbase + B_OFF + (c & 3) * 10240;
        const __half* src0 = g_W1h + c * 32;
#pragma unroll
        for (int i = 0; i < 2; i++) {
            int idx = tid + i * 256;             // 512 x 16B = 128 rows x 32 halves
            int u = idx >> 2, kk = idx & 3;
            cp16(base + u * 80 + kk * 16, src0 + u * DD + kk * 8);
        }
    };
    const int ar  = tid >> 3;                    // base row for A staging
    const int ac4 = tid & 7;                     // float4 column within chunk
    float4 av[4];
    auto ldgA = [&](int trow0, int c) {
        const float* src0 = values + (size_t)trow0 * DD + c * 32 + ac4 * 4;
#pragma unroll
        for (int i = 0; i < 4; i++)
            av[i] = *(const float4*)(src0 + (size_t)(ar + i * 32) * DD);
    };
    auto stsA = [&](int c) {
#pragma unroll
        for (int i = 0; i < 4; i++) {
            __half2 h0 = __floats2half2_rn(av[i].x, av[i].y);
            __half2 h1 = __floats2half2_rn(av[i].z, av[i].w);
            uint2 u2 = make_uint2(h2_bits(h0), h2_bits(h1));
            *(uint2*)(smem + A_OFF + (ar + i * 32) * AROW + c * 64 + ac4 * 8) = u2;
        }
    };

    // fragment address components
    const int a_r  = 32 * rg + mrow + 8 * (mi & 1);
    const int a_kb = (mi >> 1) * 16;
    const int b_n  = 64 * ch + mrow + 8 * (mi >> 1);
    const int b_kb = (mi & 1) * 16;

    // ---- first-tile prefetch ----
    int tile = blockIdx.x;
    ldgA(tile * MT, 0);
    stageB(0); stageB(1); cp_commit();

    for (; tile < NCTA; tile += PGRID) {
        const int row0 = tile * MT;
        const int b    = tile >> 6;              // 64 tiles per batch

        if (tid < UU) {
            s_hq[tid] = g_hq[b * UU + tid];
            s_b1[tid] = W1b[tid];
            s_v[tid]  = Vk[tid];
        }
        __syncthreads();                         // prev epilogue done; A writable
        // ---- preamble: A chunks 0,1 into smem; av <- chunk 2 ----
        stsA(0);
        ldgA(row0, 1);
        stsA(1);
        ldgA(row0, 2);
        cp_wait0();                              // B chunks 0,1 arrived
        __syncthreads();

        float acc[2][8][4];
#pragma unroll
        for (int m = 0; m < 2; m++)
#pragma unroll
            for (int j = 0; j < 8; j++)
#pragma unroll
                for (int q = 0; q < 4; q++) acc[m][j][q] = 0.0f;

        // ---- mainloop: 4 iterations x 2 chunks, one barrier each ----
#pragma unroll
        for (int it = 0; it < 4; it++) {
            const int c0 = 2 * it;
            if (it < 3) { stageB(c0 + 2); stageB(c0 + 3); cp_commit(); }
#pragma unroll
            for (int half = 0; half < 2; half++) {
                const int c = c0 + half;
                const uint32_t abase = sbase + A_OFF + c * 64;
                const uint32_t bbase = sbase + B_OFF + (c & 3) * 10240;
#pragma unroll
                for (int ks = 0; ks < 2; ks++) {
                    const int k0 = ks * 32;
                    uint32_t a0[4], a1[4];
                    ldsm4(a0, abase + (a_r)      * AROW + a_kb + k0);
                    ldsm4(a1, abase + (a_r + 16) * AROW + a_kb + k0);
#pragma unroll
                    for (int nt = 0; nt < 4; nt++) {
                        uint32_t bq[4];
                        ldsm4(bq, bbase + (b_n + 16 * nt) * 80 + b_kb + k0);
                        mma_f16(acc[0][2 * nt],     a0[0], a0[1], a0[2], a0[3], bq[0], bq[1]);
                        mma_f16(acc[0][2 * nt + 1], a0[0], a0[1], a0[2], a0[3], bq[2], bq[3]);
                        mma_f16(acc[1][2 * nt],     a1[0], a1[1], a1[2], a1[3], bq[0], bq[1]);
                        mma_f16(acc[1][2 * nt + 1], a1[0], a1[1], a1[2], a1[3], bq[2], bq[3]);
                    }
                }
                if (half == 0) {                 // between the two MMA bursts
                    if (it < 3) { stsA(c0 + 2); ldgA(row0, c0 + 3); }
                } else {
                    if (it < 2)      { stsA(c0 + 3); ldgA(row0, c0 + 4); }
                    else if (it == 2){ stsA(7); }
                }
            }
            if (it < 3) cp_wait0();
            __syncthreads();
        }

        // ---- prefetch next tile (overlaps epilogue) ----
        {
            int ntile = tile + PGRID;
            if (ntile < NCTA) {
                ldgA(ntile * MT, 0);
                stageB(0); stageB(1); cp_commit();
            }
        }

        // ---- epilogue 1: per-row score partials (this warp's 64-col half) ----
        float s[4] = {0.f, 0.f, 0.f, 0.f};
#pragma unroll
        for (int j = 0; j < 8; j++) {
            const int u0 = 64 * ch + 8 * j + 2 * tg;
            const int u1 = u0 + 1;
            const float v0 = s_v[u0], v1 = s_v[u1];
            const float h0 = s_hq[u0], h1 = s_hq[u1];
            const float c0 = s_b1[u0], c1 = s_b1[u1];
#pragma unroll
            for (int m = 0; m < 2; m++) {
                s[2 * m]     += v0 * tanh_fast(fmaxf(acc[m][j][0] + c0, 0.f) + h0)
                              + v1 * tanh_fast(fmaxf(acc[m][j][1] + c1, 0.f) + h1);
                s[2 * m + 1] += v0 * tanh_fast(fmaxf(acc[m][j][2] + c0, 0.f) + h0)
                              + v1 * tanh_fast(fmaxf(acc[m][j][3] + c1, 0.f) + h1);
            }
        }
#pragma unroll
        for (int i = 0; i < 4; i++) {
            s[i] += __shfl_xor_sync(0xffffffffu, s[i], 1);
            s[i] += __shfl_xor_sync(0xffffffffu, s[i], 2);
        }
        if (tg == 0) {
            const int rb = 32 * rg + g;
            s_sc[ch * 128 + rb]      = s[0];
            s_sc[ch * 128 + rb + 8]  = s[1];
            s_sc[ch * 128 + rb + 16] = s[2];
            s_sc[ch * 128 + rb + 24] = s[3];
        }
        __syncthreads();

        // ---- epilogue 2: combine halves, local max / exp / sum ----
        float myv = -3.0e38f;
        if (tid < 128) {
            myv = s_sc[tid] + s_sc[128 + tid] + Vb[0];
            g_scores[row0 + tid] = myv;
        }
        float m = myv;
#pragma unroll
        for (int o = 16; o > 0; o >>= 1) m = fmaxf(m, __shfl_xor_sync(0xffffffffu, m, o));
        if (lane == 0 && wid < 4) s_rd[wid] = m;
        __syncthreads();
        if (tid == 0) {
            s_rd[32] = fmaxf(fmaxf(s_rd[0], s_rd[1]), fmaxf(s_rd[2], s_rd[3]));
        }
        __syncthreads();
        const float mloc = s_rd[32];
        float e = (tid < 128) ? __expf(myv - mloc) : 0.0f;
        if (tid < 128) s_es[tid] = e;
        float sum = e;
#pragma unroll
        for (int o = 16; o > 0; o >>= 1) sum += __shfl_xor_sync(0xffffffffu, sum, o);
        if (lane == 0 && wid < 4) s_rd[8 + wid] = sum;
        __syncthreads();
        if (tid == 0) {
            g_stats[tile * 2]     = mloc;
            g_stats[tile * 2 + 1] = s_rd[8] + s_rd[9] + s_rd[10] + s_rd[11];
        }

        // ---- epilogue 3: partial context from persistent SMEM fp16 A tile ----
        {
            float a = 0.0f;
#pragma unroll 8
            for (int r = 0; r < MT; r++) {
                __half hv = *(const __half*)(smem + A_OFF + r * AROW + tid * 2);
                a += s_es[r] * __half2float(hv);
            }
            g_pctx[tile * DD + tid] = a;
        }
        // no sync here: next-iteration preamble syncs before touching A/s_es
    }
}

// ---------------------------------------------------------------------------
// per-batch rescale + context reduction (64 partials per batch), parallel
// ---------------------------------------------------------------------------
__global__ void reduce_kernel(float* __restrict__ ctx) {
    __shared__ float coef[64], red[8];
    const int b = blockIdx.x, tid = threadIdx.x, lane = tid & 31, w = tid >> 5;
    float val = 0.0f, cs = 0.0f;
    float m = -3.0e38f;
    if (tid < 64) {
        val = g_stats[(b * 64 + tid) * 2];
        cs  = g_stats[(b * 64 + tid) * 2 + 1];
        m = val;
    }
#pragma unroll
    for (int o = 16; o > 0; o >>= 1) m = fmaxf(m, __shfl_xor_sync(0xffffffffu, m, o));
    if (tid < 64 && lane == 0) red[w] = m;
    __syncthreads();
    if (tid == 0) red[2] = fmaxf(red[0], red[1]);
    __syncthreads();
    const float M = red[2];
    float c = 0.0f;
    if (tid < 64) {
        c = __expf(val - M);
        coef[tid] = c;
        c *= cs;
    }
#pragma unroll
    for (int o = 16; o > 0; o >>= 1) c += __shfl_xor_sync(0xffffffffu, c, o);
    if (tid < 64 && lane == 0) red[4 + w] = c;
    __syncthreads();
    if (tid == 0) {
        float S = red[4] + red[5];
        red[6] = 1.0f / S;
        g_bstats[b * 2] = M;
        g_bstats[b * 2 + 1] = 1.0f / S;
    }
    __syncthreads();
    const float inv = red[6];
    float acc = 0.0f;
#pragma unroll
    for (int k = 0; k < 64; k++) acc += coef[k] * g_pctx[(b * 64 + k) * DD + tid];
    ctx[b * DD + tid] = acc * inv;
}

// normalized attention weights (float4-vectorized)
__global__ void weights_kernel(float* __restrict__ w) {
    int i = blockIdx.x * 256 + threadIdx.x;      // float4 index; 65536 total
    int b = i >> 11;                             // 2048 float4 per batch
    float4 sc = ((const float4*)g_scores)[i];
    const float M = g_bstats[b * 2];
    const float inv = g_bstats[b * 2 + 1];
    float4 o;
    o.x = __expf(sc.x - M) * inv;
    o.y = __expf(sc.y - M) * inv;
    o.z = __expf(sc.z - M) * inv;
    o.w = __expf(sc.w - M) * inv;
    ((float4*)w)[i] = o;
}

// ---------------------------------------------------------------------------
extern "C" void kernel_launch(void* const* d_in, const int* in_sizes, int n_in,
                              void* d_out, int out_size) {
    const float* query  = (const float*)d_in[0];
    const float* values = (const float*)d_in[1];
    const float* W1     = (const float*)d_in[2];
    const float* W1b    = (const float*)d_in[3];
    const float* W2     = (const float*)d_in[4];
    const float* W2b    = (const float*)d_in[5];
    const float* Vk     = (const float*)d_in[6];
    const float* Vb     = (const float*)d_in[7];

    float* out = (float*)d_out;
    float* ctx = out;               // [B, D]
    float* wts = out + BB * DD;     // [B, T, 1]

    static bool attr_set = false;
    if (!attr_set) {
        cudaFuncSetAttribute(scores_kernel, cudaFuncAttributeMaxDynamicSharedMemorySize,
                             SMEM_BYTES);
        attr_set = true;
    }

    prep_kernel<<<160, 256>>>(query, W2, W2b, W1);
    scores_kernel<<<PGRID, 256, SMEM_BYTES>>>(values, W1b, Vk, Vb);
    reduce_kernel<<<BB, 256>>>(ctx);
    weights_kernel<<<256, 256>>>(wts);
}

// round 12
// speedup vs baseline: 1.0011x; 1.0011x over previous
#include <cuda_runtime.h>
#include <cuda_fp16.h>
#include <cstdint>

#define BB 32
#define TT 8192
#define DD 256
#define UU 128
#define MT 128
#define NCTA ((BB * TT) / MT)   // 2048 tiles, 64 per batch
#define PGRID 296               // persistent grid: 2 CTAs/SM

#define AROW 528                 // A row stride BYTES: 512 payload + 16 pad
// ---- dynamic SMEM layout (bytes) ----
#define A_OFF   0                // 128 rows x 528B = 67584 (full fp16 tile)
#define B_OFF   67584            // 4 x (128 rows x 80B) = 40960
#define SC_OFF  108544           // [2][128] floats = 1024
#define ES_OFF  109568           // 128 floats
#define HQ_OFF  110080           // 128 floats
#define B1_OFF  110592           // 128 floats
#define VV_OFF  111104           // 128 floats
#define RED_OFF 111616           // 64 floats
#define SMEM_BYTES 112128

// ---- scratch globals (allocation-free) ----
__device__ float  g_hq[BB * UU];
__device__ __half g_W1h[UU * DD];       // W1 transposed -> [u][d], fp16
__device__ float  g_scores[BB * TT];
__device__ float  g_stats[NCTA * 2];    // per-tile (local max, local expsum)
__device__ float  g_pctx[NCTA * DD];    // per-tile unnormalized partial context
__device__ float  g_bstats[BB * 2];     // per-batch (global max, 1/sum)

// ---------------------------------------------------------------------------
// helpers
// ---------------------------------------------------------------------------
__device__ __forceinline__ uint32_t smem_u32(const void* p) {
    uint32_t a;
    asm("{ .reg .u64 t; cvta.to.shared.u64 t, %1; cvt.u32.u64 %0, t; }" : "=r"(a) : "l"(p));
    return a;
}
__device__ __forceinline__ void ldsm4p(uint32_t* r, uint32_t addr) {
    asm volatile("ldmatrix.sync.aligned.m8n8.x4.shared.b16 {%0,%1,%2,%3}, [%4];"
                 : "=r"(r[0]), "=r"(r[1]), "=r"(r[2]), "=r"(r[3]) : "r"(addr));
}
// NOT volatile: pure register op; scheduling freedom for ptxas
__device__ __forceinline__ void mma_f16(float c[4],
                                        uint32_t a0, uint32_t a1, uint32_t a2, uint32_t a3,
                                        uint32_t b0, uint32_t b1) {
    asm("mma.sync.aligned.m16n8k16.row.col.f32.f16.f16.f32 "
        "{%0,%1,%2,%3}, {%4,%5,%6,%7}, {%8,%9}, {%0,%1,%2,%3};"
        : "+f"(c[0]), "+f"(c[1]), "+f"(c[2]), "+f"(c[3])
        : "r"(a0), "r"(a1), "r"(a2), "r"(a3), "r"(b0), "r"(b1));
}
__device__ __forceinline__ void cp16(uint32_t dst, const void* src) {
    asm volatile("cp.async.cg.shared.global [%0], [%1], 16;"
                 :: "r"(dst), "l"(src) : "memory");
}
__device__ __forceinline__ void cp_commit() {
    asm volatile("cp.async.commit_group;" ::: "memory");
}
__device__ __forceinline__ void cp_wait0() {
    asm volatile("cp.async.wait_group 0;" ::: "memory");
}
__device__ __forceinline__ uint32_t h2_bits(__half2 h) {
    union { __half2 h; uint32_t u; } cvt;
    cvt.h = h;
    return cvt.u;
}
__device__ __forceinline__ float tanh_fast(float x) {   // 1 MUFU, ~5e-4 abs err
    float y;
    asm("tanh.approx.f32 %0, %1;" : "=f"(y) : "f"(x));
    return y;
}

// ---------------------------------------------------------------------------
// fused prep: blocks 0..31 -> hq, blocks 32..159 -> W1 transpose+fp16
// ---------------------------------------------------------------------------
__global__ void prep_kernel(const float* __restrict__ query,
                            const float* __restrict__ W2,
                            const float* __restrict__ W2b,
                            const float* __restrict__ W1) {
    if (blockIdx.x < 32) {
        if (threadIdx.x < UU) {
            int b = blockIdx.x, u = threadIdx.x;
            const float* q = query + b * DD;
            float acc = 0.0f;
#pragma unroll 8
            for (int d = 0; d < DD; d++) acc += q[d] * W2[d * UU + u];
            g_hq[b * UU + u] = fmaxf(acc + W2b[u], 0.0f);
        }
    } else {
        int u = blockIdx.x - 32, d = threadIdx.x;
        g_W1h[u * DD + d] = __float2half_rn(W1[d * UU + u]);
    }
}

// ---------------------------------------------------------------------------
// persistent fused kernel; register-pipelined fp16 mma mainloop.
// 296 CTAs x 256 threads; warp = (rg 0..3, ch 0..1).
// ---------------------------------------------------------------------------
__global__ __launch_bounds__(256, 2)
void scores_kernel(const float* __restrict__ values,
                   const float* __restrict__ W1b,
                   const float* __restrict__ Vk,
                   const float* __restrict__ Vb) {
    extern __shared__ char smem[];
    const uint32_t sbase = smem_u32(smem);
    const int tid  = threadIdx.x;
    const int wid  = tid >> 5;
    const int lane = tid & 31;
    const int rg   = wid >> 1;
    const int ch   = wid & 1;
    const int mrow = lane & 7;
    const int mi   = lane >> 3;
    const int tg   = lane & 3;
    const int g    = lane >> 2;

    float* s_sc = (float*)(smem + SC_OFF);
    float* s_es = (float*)(smem + ES_OFF);
    float* s_hq = (float*)(smem + HQ_OFF);
    float* s_b1 = (float*)(smem + B1_OFF);
    float* s_v  = (float*)(smem + VV_OFF);
    float* s_rd = (float*)(smem + RED_OFF);

    // ---- staging helpers ----
    auto stageB = [&](int c) {                   // cp.async, 4-buffer ring
        const uint32_t base = sbase + B_OFF + (c & 3) * 10240;
        const __half* src0 = g_W1h + c * 32;
#pragma unroll
        for (int i = 0; i < 2; i++) {
            int idx = tid + i * 256;             // 512 x 16B = 128 rows x 32 halves
            int u = idx >> 2, kk = idx & 3;
            cp16(base + u * 80 + kk * 16, src0 + u * DD + kk * 8);
        }
    };
    const int ar  = tid >> 3;                    // base row for A staging
    const int ac4 = tid & 7;                     // float4 column within chunk
    uint2 avh[4];                                // fp16-converted staged data
    auto ldgA = [&](int trow0, int c) {
        const float* src0 = values + (size_t)trow0 * DD + c * 32 + ac4 * 4;
#pragma unroll
        for (int i = 0; i < 4; i++) {
            float4 v = *(const float4*)(src0 + (size_t)(ar + i * 32) * DD);
            avh[i] = make_uint2(h2_bits(__floats2half2_rn(v.x, v.y)),
                                h2_bits(__floats2half2_rn(v.z, v.w)));
        }
    };
    auto stsA = [&](int c) {
#pragma unroll
        for (int i = 0; i < 4; i++)
            *(uint2*)(smem + A_OFF + (ar + i * 32) * AROW + c * 64 + ac4 * 8) = avh[i];
    };

    // fragment address components
    const int a_r  = 32 * rg + mrow + 8 * (mi & 1);
    const int a_kb = (mi >> 1) * 16;
    const int b_n  = 64 * ch + mrow + 8 * (mi >> 1);
    const int b_kb = (mi & 1) * 16;

    // fragment loaders: q = 0..3 within an 'it' (chunk c0 + (q>>1), k half q&1)
    auto lda = [&](uint32_t* dst, int c0, int q) {
        const uint32_t abase = sbase + A_OFF + (c0 + (q >> 1)) * 64 + (q & 1) * 32;
        ldsm4p(dst,     abase + (a_r)      * AROW + a_kb);
        ldsm4p(dst + 4, abase + (a_r + 16) * AROW + a_kb);
    };
    auto ldb = [&](uint32_t* dst, int c0, int q, int nt) {
        const int c = c0 + (q >> 1);
        const uint32_t bbase = sbase + B_OFF + (c & 3) * 10240 + (q & 1) * 32;
        ldsm4p(dst, bbase + (b_n + 16 * nt) * 80 + b_kb);
    };

    // ---- first-tile prefetch ----
    int tile = blockIdx.x;
    ldgA(tile * MT, 0);
    stageB(0); stageB(1); cp_commit();

    for (; tile < NCTA; tile += PGRID) {
        const int row0 = tile * MT;
        const int b    = tile >> 6;              // 64 tiles per batch

        if (tid < UU) {
            s_hq[tid] = g_hq[b * UU + tid];
            s_b1[tid] = W1b[tid];
            s_v[tid]  = Vk[tid];
        }
        __syncthreads();                         // prev epilogue done; A writable
        // ---- preamble: A chunks 0,1 into smem; avh <- chunk 2 ----
        stsA(0);
        ldgA(row0, 1);
        stsA(1);
        ldgA(row0, 2);
        cp_wait0();                              // B chunks 0,1 arrived
        __syncthreads();

        float acc[2][8][4];
#pragma unroll
        for (int m = 0; m < 2; m++)
#pragma unroll
            for (int j = 0; j < 8; j++)
#pragma unroll
                for (int q = 0; q < 4; q++) acc[m][j][q] = 0.0f;

        // ---- mainloop: 4 its x (2 chunks = 4 q-steps), reg-pipelined ----
#pragma unroll
        for (int it = 0; it < 4; it++) {
            const int c0 = 2 * it;
            if (it < 3) { stageB(c0 + 2); stageB(c0 + 3); cp_commit(); }

            uint32_t afr[2][8], bfr[2][4];
            lda(afr[0], c0, 0);
            ldb(bfr[0], c0, 0, 0);
#pragma unroll
            for (int q = 0; q < 4; q++) {
                const int pq = q & 1;
                if (q < 3) lda(afr[pq ^ 1], c0, q + 1);   // prefetch next A
#pragma unroll
                for (int nt = 0; nt < 4; nt++) {
                    const int pb = nt & 1;
                    if (nt < 3)      ldb(bfr[pb ^ 1], c0, q, nt + 1);
                    else if (q < 3)  ldb(bfr[pb ^ 1], c0, q + 1, 0);
                    const uint32_t* A = afr[pq];
                    const uint32_t* Bq = bfr[pb];
                    mma_f16(acc[0][2 * nt],     A[0], A[1], A[2], A[3], Bq[0], Bq[1]);
                    mma_f16(acc[0][2 * nt + 1], A[0], A[1], A[2], A[3], Bq[2], Bq[3]);
                    mma_f16(acc[1][2 * nt],     A[4], A[5], A[6], A[7], Bq[0], Bq[1]);
                    mma_f16(acc[1][2 * nt + 1], A[4], A[5], A[6], A[7], Bq[2], Bq[3]);
                }
                // interleave A global staging between q-steps
                if (q == 1) {
                    if (it < 3) { stsA(c0 + 2); ldgA(row0, c0 + 3); }
                } else if (q == 3) {
                    if (it < 2)       { stsA(c0 + 3); ldgA(row0, c0 + 4); }
                    else if (it == 2) { stsA(7); }
                }
            }
            if (it < 3) cp_wait0();
            __syncthreads();
        }

        // ---- prefetch next tile (overlaps epilogue) ----
        {
            int ntile = tile + PGRID;
            if (ntile < NCTA) {
                ldgA(ntile * MT, 0);
                stageB(0); stageB(1); cp_commit();
            }
        }

        // ---- epilogue 1: per-row score partials (this warp's 64-col half) ----
        float s[4] = {0.f, 0.f, 0.f, 0.f};
#pragma unroll
        for (int j = 0; j < 8; j++) {
            const int u0 = 64 * ch + 8 * j + 2 * tg;
            const int u1 = u0 + 1;
            const float v0 = s_v[u0], v1 = s_v[u1];
            const float h0 = s_hq[u0], h1 = s_hq[u1];
            const float c0 = s_b1[u0], c1 = s_b1[u1];
#pragma unroll
            for (int m = 0; m < 2; m++) {
                s[2 * m]     += v0 * tanh_fast(fmaxf(acc[m][j][0] + c0, 0.f) + h0)
                              + v1 * tanh_fast(fmaxf(acc[m][j][1] + c1, 0.f) + h1);
                s[2 * m + 1] += v0 * tanh_fast(fmaxf(acc[m][j][2] + c0, 0.f) + h0)
                              + v1 * tanh_fast(fmaxf(acc[m][j][3] + c1, 0.f) + h1);
            }
        }
#pragma unroll
        for (int i = 0; i < 4; i++) {
            s[i] += __shfl_xor_sync(0xffffffffu, s[i], 1);
            s[i] += __shfl_xor_sync(0xffffffffu, s[i], 2);
        }
        if (tg == 0) {
            const int rb = 32 * rg + g;
            s_sc[ch * 128 + rb]      = s[0];
            s_sc[ch * 128 + rb + 8]  = s[1];
            s_sc[ch * 128 + rb + 16] = s[2];
            s_sc[ch * 128 + rb + 24] = s[3];
        }
        __syncthreads();

        // ---- epilogue 2: combine halves, local max / exp / sum ----
        float myv = -3.0e38f;
        if (tid < 128) {
            myv = s_sc[tid] + s_sc[128 + tid] + Vb[0];
            g_scores[row0 + tid] = myv;
        }
        float m = myv;
#pragma unroll
        for (int o = 16; o > 0; o >>= 1) m = fmaxf(m, __shfl_xor_sync(0xffffffffu, m, o));
        if (lane == 0 && wid < 4) s_rd[wid] = m;
        __syncthreads();
        if (tid == 0) {
            s_rd[32] = fmaxf(fmaxf(s_rd[0], s_rd[1]), fmaxf(s_rd[2], s_rd[3]));
        }
        __syncthreads();
        const float mloc = s_rd[32];
        float e = (tid < 128) ? __expf(myv - mloc) : 0.0f;
        if (tid < 128) s_es[tid] = e;
        float sum = e;
#pragma unroll
        for (int o = 16; o > 0; o >>= 1) sum += __shfl_xor_sync(0xffffffffu, sum, o);
        if (lane == 0 && wid < 4) s_rd[8 + wid] = sum;
        __syncthreads();
        if (tid == 0) {
            g_stats[tile * 2]     = mloc;
            g_stats[tile * 2 + 1] = s_rd[8] + s_rd[9] + s_rd[10] + s_rd[11];
        }

        // ---- epilogue 3: partial context from persistent SMEM fp16 A tile ----
        {
            float a = 0.0f;
#pragma unroll 8
            for (int r = 0; r < MT; r++) {
                __half hv = *(const __half*)(smem + A_OFF + r * AROW + tid * 2);
                a += s_es[r] * __half2float(hv);
            }
            g_pctx[tile * DD + tid] = a;
        }
        // no sync: next-iteration preamble syncs before touching A/s_es
    }
}

// ---------------------------------------------------------------------------
// per-batch rescale + context reduction (64 partials per batch), parallel
// ---------------------------------------------------------------------------
__global__ void reduce_kernel(float* __restrict__ ctx) {
    __shared__ float coef[64], red[8];
    const int b = blockIdx.x, tid = threadIdx.x, lane = tid & 31, w = tid >> 5;
    float val = 0.0f, cs = 0.0f;
    float m = -3.0e38f;
    if (tid < 64) {
        val = g_stats[(b * 64 + tid) * 2];
        cs  = g_stats[(b * 64 + tid) * 2 + 1];
        m = val;
    }
#pragma unroll
    for (int o = 16; o > 0; o >>= 1) m = fmaxf(m, __shfl_xor_sync(0xffffffffu, m, o));
    if (tid < 64 && lane == 0) red[w] = m;
    __syncthreads();
    if (tid == 0) red[2] = fmaxf(red[0], red[1]);
    __syncthreads();
    const float M = red[2];
    float c = 0.0f;
    if (tid < 64) {
        c = __expf(val - M);
        coef[tid] = c;
        c *= cs;
    }
#pragma unroll
    for (int o = 16; o > 0; o >>= 1) c += __shfl_xor_sync(0xffffffffu, c, o);
    if (tid < 64 && lane == 0) red[4 + w] = c;
    __syncthreads();
    if (tid == 0) {
        float S = red[4] + red[5];
        red[6] = 1.0f / S;
        g_bstats[b * 2] = M;
        g_bstats[b * 2 + 1] = 1.0f / S;
    }
    __syncthreads();
    const float inv = red[6];
    float acc = 0.0f;
#pragma unroll
    for (int k = 0; k < 64; k++) acc += coef[k] * g_pctx[(b * 64 + k) * DD + tid];
    ctx[b * DD + tid] = acc * inv;
}

// normalized attention weights (float4-vectorized)
__global__ void weights_kernel(float* __restrict__ w) {
    int i = blockIdx.x * 256 + threadIdx.x;      // float4 index; 65536 total
    int b = i >> 11;                             // 2048 float4 per batch
    float4 sc = ((const float4*)g_scores)[i];
    const float M = g_bstats[b * 2];
    const float inv = g_bstats[b * 2 + 1];
    float4 o;
    o.x = __expf(sc.x - M) * inv;
    o.y = __expf(sc.y - M) * inv;
    o.z = __expf(sc.z - M) * inv;
    o.w = __expf(sc.w - M) * inv;
    ((float4*)w)[i] = o;
}

// ---------------------------------------------------------------------------
extern "C" void kernel_launch(void* const* d_in, const int* in_sizes, int n_in,
                              void* d_out, int out_size) {
    const float* query  = (const float*)d_in[0];
    const float* W1     = (const float*)d_in[2];
    const float* values = (const float*)d_in[1];
    const float* W1b    = (const float*)d_in[3];
    const float* W2     = (const float*)d_in[4];
    const float* W2b    = (const float*)d_in[5];
    const float* Vk     = (const float*)d_in[6];
    const float* Vb     = (const float*)d_in[7];

    float* out = (float*)d_out;
    float* ctx = out;               // [B, D]
    float* wts = out + BB * DD;     // [B, T, 1]

    static bool attr_set = false;
    if (!attr_set) {
        cudaFuncSetAttribute(scores_kernel, cudaFuncAttributeMaxDynamicSharedMemorySize,
                             SMEM_BYTES);
        attr_set = true;
    }

    prep_kernel<<<160, 256>>>(query, W2, W2b, W1);
    scores_kernel<<<PGRID, 256, SMEM_BYTES>>>(values, W1b, Vk, Vb);
    reduce_kernel<<<BB, 256>>>(ctx);
    weights_kernel<<<256, 256>>>(wts);
}